// round 4
// baseline (speedup 1.0000x reference)
#include <cuda_runtime.h>

#define HW     4096
#define WIDTH  64
#define CDIM   256
#define NH     8
#define HD     32
#define BATCH  2
#define SCALE  0.17677669529663687f

// Scratch (device globals; no allocation allowed)
__device__ float g_q[BATCH * NH * HW * HD];      // [b, head, p, d]
__device__ float g_k[BATCH * NH * HW * HD];      // [b, head, p, d]
__device__ float g_v[BATCH * NH * HW * HD];      // [b, head, p, d]
__device__ float g_attn[BATCH * HW * CDIM];      // [b, p, c]  c = head*32+d

// ---------------------------------------------------------------------------
// Kernel 1: QKV projection (proven R1 version, 64x64 tile, 4x4 microtile).
// ---------------------------------------------------------------------------
__global__ __launch_bounds__(256) void qkv_gemm_kernel(
    const float* __restrict__ x,
    const float* __restrict__ w0, const float* __restrict__ bb0,
    const float* __restrict__ w1, const float* __restrict__ bb1,
    const float* __restrict__ w2, const float* __restrict__ bb2)
{
    __shared__ float As[64][16];
    __shared__ float Bs[16][68];
    __shared__ const float* Arow[64];
    __shared__ float biasS[64];

    const int tid  = threadIdx.x;
    const int row0 = blockIdx.y * 64;
    const int col0 = blockIdx.x * 64;
    const int b    = blockIdx.z;

    if (tid < 64) {
        int M = row0 + tid;
        int t = M >> 8;            // 0=q, 1=k, 2=v
        int rem = M & 255;         // head*32 + d
        int head = rem >> 5;
        const float* w; const float* bb;
        if (head < 4)      { w = w0; bb = bb0; }
        else if (head < 7) { w = w1; bb = bb1; }
        else               { w = w2; bb = bb2; }
        Arow[tid]  = w + (size_t)(t * 256 + rem) * 256;
        biasS[tid] = bb[t * 256 + rem];
    }
    __syncthreads();

    const int tx = tid & 15, ty = tid >> 4;
    float acc[4][4] = {};
    const float* xb = x + (size_t)b * CDIM * HW;

    for (int k0 = 0; k0 < 256; k0 += 16) {
        {
            int m = tid >> 2, k = (tid & 3) * 4;
            float4 av = *(const float4*)(Arow[m] + k0 + k);
            *(float4*)&As[m][k] = av;
        }
        {
            int k = tid >> 4, n = (tid & 15) * 4;
            float4 bv = *(const float4*)(xb + (size_t)(k0 + k) * HW + col0 + n);
            *(float4*)&Bs[k][n] = bv;
        }
        __syncthreads();
        #pragma unroll
        for (int kk = 0; kk < 16; kk++) {
            float a[4];
            #pragma unroll
            for (int i = 0; i < 4; i++) a[i] = As[ty * 4 + i][kk];
            float4 bv = *(float4*)&Bs[kk][tx * 4];
            float bl[4] = {bv.x, bv.y, bv.z, bv.w};
            #pragma unroll
            for (int i = 0; i < 4; i++)
                #pragma unroll
                for (int j = 0; j < 4; j++)
                    acc[i][j] += a[i] * bl[j];
        }
        __syncthreads();
    }

    #pragma unroll
    for (int i = 0; i < 4; i++) {
        int M = row0 + ty * 4 + i;
        int t = M >> 8, rem = M & 255, head = rem >> 5, d = rem & 31;
        float* dst = (t == 0) ? g_q : (t == 1) ? g_k : g_v;
        float bias = biasS[ty * 4 + i];
        int base = ((b * NH + head) * HW) * HD + d;
        #pragma unroll
        for (int j = 0; j < 4; j++) {
            int p = col0 + tx * 4 + j;
            dst[base + p * HD] = acc[i][j] + bias;
        }
    }
}

// ---------------------------------------------------------------------------
// Neighborhood attention body (proven R3 butterfly version). One warp per
// (b, head, pixel); lane = d. Logits via 31-shuffle butterfly transpose-
// reduction; OOB neighbors keep logit = 0 inside the softmax.
// ---------------------------------------------------------------------------
template <int KSZ, int DIL>
__device__ __forceinline__ void attn_body(int lane, int b, int head, int p)
{
    constexpr int L = KSZ * KSZ;
    constexpr int NL = (L + 31) / 32;
    constexpr int HALF = KSZ / 2;

    const int y = p >> 6, x = p & 63;
    const int hb = ((b * NH + head) * HW) * HD;
    const float* __restrict__ kb = g_k + hb;
    const float* __restrict__ vb = g_v + hb;

    const float q = g_q[hb + p * HD + lane] * SCALE;

    float lgs[NL];
    #pragma unroll
    for (int batch = 0; batch < NL; batch++) {
        float v[32];
        #pragma unroll
        for (int j = 0; j < 32; j++) {
            const int idx = batch * 32 + j;
            float kval = 0.f;
            if (idx < L) {
                const int ky = idx / KSZ, kx = idx % KSZ;
                const int ny = y + (ky - HALF) * DIL;
                const int nx = x + (kx - HALF) * DIL;
                if ((unsigned)ny < 64u && (unsigned)nx < 64u)
                    kval = kb[(ny * 64 + nx) * HD + lane];
            }
            v[j] = q * kval;
        }
        #pragma unroll
        for (int m = 16; m >= 1; m >>= 1) {
            const bool up = (lane & m) != 0;
            #pragma unroll
            for (int j = 0; j < m; j++) {
                float send = up ? v[j] : v[j + m];
                float recv = __shfl_xor_sync(0xffffffffu, send, m);
                v[j] = (up ? v[j + m] : v[j]) + recv;
            }
        }
        lgs[batch] = v[0];
    }

    float mx = -1e30f;
    #pragma unroll
    for (int j = 0; j < NL; j++)
        if (j * 32 + lane < L) mx = fmaxf(mx, lgs[j]);
    #pragma unroll
    for (int o = 16; o > 0; o >>= 1)
        mx = fmaxf(mx, __shfl_xor_sync(0xffffffffu, mx, o));

    float e[NL];
    float sum = 0.f;
    #pragma unroll
    for (int j = 0; j < NL; j++) {
        e[j] = (j * 32 + lane < L) ? __expf(lgs[j] - mx) : 0.f;
        sum += e[j];
    }
    #pragma unroll
    for (int o = 16; o > 0; o >>= 1)
        sum += __shfl_xor_sync(0xffffffffu, sum, o);
    const float inv = 1.f / sum;

    float acc = 0.f;
    #pragma unroll
    for (int ky = 0; ky < KSZ; ky++) {
        const int ny = y + (ky - HALF) * DIL;
        #pragma unroll
        for (int kx = 0; kx < KSZ; kx++) {
            const int l = ky * KSZ + kx;
            const int nx = x + (kx - HALF) * DIL;
            if ((unsigned)ny < 64u && (unsigned)nx < 64u) {
                float pl = __shfl_sync(0xffffffffu, e[l >> 5], l & 31) * inv;
                acc += pl * vb[(ny * 64 + nx) * HD + lane];
            }
        }
    }

    g_attn[(b * HW + p) * CDIM + head * HD + lane] = acc;
}

// Range 0: heads 0-3 (k=5, dil=1). One warp per (b, head, pixel).
__global__ __launch_bounds__(128) void attn_r0_kernel()
{
    const int lane = threadIdx.x & 31;
    const int wid  = threadIdx.x >> 5;
    const int W    = blockIdx.x * 4 + wid;       // over B*4*HW
    const int p    = W & (HW - 1);
    const int head = (W >> 12) & 3;
    const int b    = W >> 14;
    attn_body<5, 1>(lane, b, head, p);
}

// Ranges 1+2: heads 4-6 (k=7, dil=2) and head 7 (k=9, dil=3).
__global__ __launch_bounds__(128) void attn_r12_kernel()
{
    const int lane = threadIdx.x & 31;
    const int wid  = threadIdx.x >> 5;
    const int W    = blockIdx.x * 4 + wid;       // over B*4*HW
    const int p    = W & (HW - 1);
    const int hrel = (W >> 12) & 3;              // 0..3 -> heads 4..7
    const int b    = W >> 14;
    if (hrel < 3) attn_body<7, 2>(lane, b, 4 + hrel, p);
    else          attn_body<9, 3>(lane, b, 7, p);
}

// ---------------------------------------------------------------------------
// Kernel 3: output projection (proven R1 version, 64x64 tile, 4x4 microtile).
// ---------------------------------------------------------------------------
__global__ __launch_bounds__(256) void proj_gemm_kernel(
    const float* __restrict__ pw, const float* __restrict__ pb,
    float* __restrict__ out)
{
    __shared__ float As[64][16];
    __shared__ float Bs[16][68];

    const int tid  = threadIdx.x;
    const int row0 = blockIdx.y * 64;
    const int col0 = blockIdx.x * 64;
    const int b    = blockIdx.z;

    const int tx = tid & 15, ty = tid >> 4;
    float acc[4][4] = {};
    const float* attb = g_attn + (size_t)b * HW * CDIM;

    for (int k0 = 0; k0 < 256; k0 += 16) {
        {
            int m = tid >> 2, k = (tid & 3) * 4;
            *(float4*)&As[m][k] =
                *(const float4*)(pw + (size_t)(row0 + m) * 256 + k0 + k);
        }
        {
            int n = tid >> 2, k = (tid & 3) * 4;
            float4 bv = *(const float4*)(attb + (size_t)(col0 + n) * CDIM + k0 + k);
            Bs[k][n]     = bv.x;
            Bs[k + 1][n] = bv.y;
            Bs[k + 2][n] = bv.z;
            Bs[k + 3][n] = bv.w;
        }
        __syncthreads();
        #pragma unroll
        for (int kk = 0; kk < 16; kk++) {
            float a[4];
            #pragma unroll
            for (int i = 0; i < 4; i++) a[i] = As[ty * 4 + i][kk];
            float4 bv = *(float4*)&Bs[kk][tx * 4];
            float bl[4] = {bv.x, bv.y, bv.z, bv.w};
            #pragma unroll
            for (int i = 0; i < 4; i++)
                #pragma unroll
                for (int j = 0; j < 4; j++)
                    acc[i][j] += a[i] * bl[j];
        }
        __syncthreads();
    }

    #pragma unroll
    for (int i = 0; i < 4; i++) {
        int o = row0 + ty * 4 + i;
        float bias = pb[o];
        float4 ov = make_float4(acc[i][0] + bias, acc[i][1] + bias,
                                acc[i][2] + bias, acc[i][3] + bias);
        *(float4*)(out + ((size_t)b * CDIM + o) * HW + col0 + tx * 4) = ov;
    }
}

// ---------------------------------------------------------------------------
extern "C" void kernel_launch(void* const* d_in, const int* in_sizes, int n_in,
                              void* d_out, int out_size)
{
    const float* x   = (const float*)d_in[0];
    const float* w0  = (const float*)d_in[1];
    const float* bb0 = (const float*)d_in[2];
    const float* w1  = (const float*)d_in[3];
    const float* bb1 = (const float*)d_in[4];
    const float* w2  = (const float*)d_in[5];
    const float* bb2 = (const float*)d_in[6];
    const float* pw  = (const float*)d_in[7];
    const float* pb  = (const float*)d_in[8];
    float* out = (float*)d_out;

    // 4 launches per call: ncu (-s 5 -c 1) captures call-2's attn_r0.
    qkv_gemm_kernel<<<dim3(HW / 64, 768 / 64, BATCH), 256>>>(
        x, w0, bb0, w1, bb1, w2, bb2);

    attn_r0_kernel<<<(BATCH * 4 * HW) / 4, 128>>>();
    attn_r12_kernel<<<(BATCH * 4 * HW) / 4, 128>>>();

    proj_gemm_kernel<<<dim3(HW / 64, CDIM / 64, BATCH), 256>>>(pw, pb, out);
}

// round 5
// speedup vs baseline: 2.0987x; 2.0987x over previous
#include <cuda_runtime.h>

#define HW     4096
#define WIDTH  64
#define CDIM   256
#define NH     8
#define HD     32
#define BATCH  2
#define SCALE  0.17677669529663687f

// Scratch (device globals; no allocation allowed)
__device__ float g_q[BATCH * NH * HW * HD];      // [b, head, p, d]
__device__ float g_k[BATCH * NH * HW * HD];      // [b, head, p, d]
__device__ float g_v[BATCH * NH * HW * HD];      // [b, head, p, d]
__device__ float g_attn[BATCH * HW * CDIM];      // [b, p, c]  c = head*32+d

// ---------------------------------------------------------------------------
// tf32 MMA helpers
// ---------------------------------------------------------------------------
__device__ __forceinline__ unsigned f2tf(float f)
{
    unsigned u;
    asm("cvt.rna.tf32.f32 %0, %1;" : "=r"(u) : "f"(f));
    return u;
}

__device__ __forceinline__ void mma8(float d[4], const unsigned a[4], const unsigned b[2])
{
    asm("mma.sync.aligned.m16n8k8.row.col.f32.tf32.tf32.f32 "
        "{%0,%1,%2,%3}, {%4,%5,%6,%7}, {%8,%9}, {%0,%1,%2,%3};"
        : "+f"(d[0]), "+f"(d[1]), "+f"(d[2]), "+f"(d[3])
        : "r"(a[0]), "r"(a[1]), "r"(a[2]), "r"(a[3]),
          "r"(b[0]), "r"(b[1]));
}

// ---------------------------------------------------------------------------
// Kernel 1: QKV projection, tf32 tensor-core. M=768 (3 types x 256 ch),
// K=256, N=4096, batch 2. Block tile 64x64, 8 warps (2x4), warp tile 32x16.
// ---------------------------------------------------------------------------
__global__ __launch_bounds__(256) void qkv_gemm_kernel(
    const float* __restrict__ x,
    const float* __restrict__ w0, const float* __restrict__ bb0,
    const float* __restrict__ w1, const float* __restrict__ bb1,
    const float* __restrict__ w2, const float* __restrict__ bb2)
{
    __shared__ unsigned As[64][36];        // [m][k] tf32, pad 36 (conflict-free)
    __shared__ unsigned Bs[32][72];        // [k][n] tf32, pad 72 (conflict-free)
    __shared__ const float* Arow[64];
    __shared__ float* rowDst[64];
    __shared__ float biasS[64];

    const int tid  = threadIdx.x;
    const int row0 = blockIdx.y * 64;
    const int col0 = blockIdx.x * 64;
    const int b    = blockIdx.z;

    if (tid < 64) {
        int M = row0 + tid;
        int t = M >> 8;            // 0=q, 1=k, 2=v
        int rem = M & 255;         // head*32 + d
        int head = rem >> 5, d = rem & 31;
        const float* w; const float* bb;
        if (head < 4)      { w = w0; bb = bb0; }
        else if (head < 7) { w = w1; bb = bb1; }
        else               { w = w2; bb = bb2; }
        Arow[tid]  = w + (size_t)(t * 256 + rem) * 256;
        biasS[tid] = bb[t * 256 + rem];
        float* dst = (t == 0) ? g_q : (t == 1) ? g_k : g_v;
        rowDst[tid] = dst + ((size_t)(b * NH + head) * HW) * HD + d;
    }
    __syncthreads();

    const int wid  = tid >> 5;
    const int lane = tid & 31;
    const int g = lane >> 2, t4 = lane & 3;
    const int m0 = (wid >> 2) * 32;            // warp m offset (0/32)
    const int n0 = (wid & 3) * 16;             // warp n offset (0/16/32/48)

    const int am = tid >> 2, ak = (tid & 3) * 8;   // A loader mapping
    const int bk = tid >> 3, bn = (tid & 7) * 8;   // B loader mapping

    const float* xb = x + (size_t)b * CDIM * HW;
    float acc[2][2][4] = {};

    for (int k0 = 0; k0 < 256; k0 += 32) {
        {   // A tile 64x32 -> tf32
            const float* src = Arow[am] + k0 + ak;
            float4 v0 = *(const float4*)(src);
            float4 v1 = *(const float4*)(src + 4);
            As[am][ak + 0] = f2tf(v0.x); As[am][ak + 1] = f2tf(v0.y);
            As[am][ak + 2] = f2tf(v0.z); As[am][ak + 3] = f2tf(v0.w);
            As[am][ak + 4] = f2tf(v1.x); As[am][ak + 5] = f2tf(v1.y);
            As[am][ak + 6] = f2tf(v1.z); As[am][ak + 7] = f2tf(v1.w);
        }
        {   // B tile 32x64 -> tf32 (x is [k][n] row-major in n)
            const float* src = xb + (size_t)(k0 + bk) * HW + col0 + bn;
            float4 v0 = *(const float4*)(src);
            float4 v1 = *(const float4*)(src + 4);
            Bs[bk][bn + 0] = f2tf(v0.x); Bs[bk][bn + 1] = f2tf(v0.y);
            Bs[bk][bn + 2] = f2tf(v0.z); Bs[bk][bn + 3] = f2tf(v0.w);
            Bs[bk][bn + 4] = f2tf(v1.x); Bs[bk][bn + 5] = f2tf(v1.y);
            Bs[bk][bn + 6] = f2tf(v1.z); Bs[bk][bn + 7] = f2tf(v1.w);
        }
        __syncthreads();
        #pragma unroll
        for (int ks = 0; ks < 4; ks++) {
            const int kk = ks * 8;
            unsigned a[2][4], bf[2][2];
            #pragma unroll
            for (int mi = 0; mi < 2; mi++) {
                const int mr = m0 + mi * 16;
                a[mi][0] = As[mr + g][kk + t4];
                a[mi][1] = As[mr + g + 8][kk + t4];
                a[mi][2] = As[mr + g][kk + t4 + 4];
                a[mi][3] = As[mr + g + 8][kk + t4 + 4];
            }
            #pragma unroll
            for (int ni = 0; ni < 2; ni++) {
                const int nc = n0 + ni * 8 + g;
                bf[ni][0] = Bs[kk + t4][nc];
                bf[ni][1] = Bs[kk + t4 + 4][nc];
            }
            #pragma unroll
            for (int mi = 0; mi < 2; mi++)
                #pragma unroll
                for (int ni = 0; ni < 2; ni++)
                    mma8(acc[mi][ni], a[mi], bf[ni]);
        }
        __syncthreads();
    }

    // Epilogue: d0,d1 -> (row g, p, p+1); d2,d3 -> (row g+8, p, p+1)
    #pragma unroll
    for (int mi = 0; mi < 2; mi++) {
        const int rl = m0 + mi * 16 + g;
        const int rh = rl + 8;
        float* dl = rowDst[rl]; const float bl = biasS[rl];
        float* dh = rowDst[rh]; const float bh = biasS[rh];
        #pragma unroll
        for (int ni = 0; ni < 2; ni++) {
            const int p = col0 + n0 + ni * 8 + 2 * t4;
            dl[(size_t)p * HD]       = acc[mi][ni][0] + bl;
            dl[(size_t)(p + 1) * HD] = acc[mi][ni][1] + bl;
            dh[(size_t)p * HD]       = acc[mi][ni][2] + bh;
            dh[(size_t)(p + 1) * HD] = acc[mi][ni][3] + bh;
        }
    }
}

// ---------------------------------------------------------------------------
// Kernel 2: neighborhood attention (proven R3 version). One warp per
// (b, head, pixel); lane = d. Logits via 31-shuffle butterfly transpose-
// reduction; OOB neighbors keep logit = 0 inside the softmax.
// ---------------------------------------------------------------------------
template <int KSZ, int DIL>
__device__ __forceinline__ void attn_body(int lane, int b, int head, int p)
{
    constexpr int L = KSZ * KSZ;
    constexpr int NL = (L + 31) / 32;
    constexpr int HALF = KSZ / 2;

    const int y = p >> 6, x = p & 63;
    const int hb = ((b * NH + head) * HW) * HD;
    const float* __restrict__ kb = g_k + hb;
    const float* __restrict__ vb = g_v + hb;

    const float q = g_q[hb + p * HD + lane] * SCALE;

    float lgs[NL];
    #pragma unroll
    for (int batch = 0; batch < NL; batch++) {
        float v[32];
        #pragma unroll
        for (int j = 0; j < 32; j++) {
            const int idx = batch * 32 + j;
            float kval = 0.f;
            if (idx < L) {
                const int ky = idx / KSZ, kx = idx % KSZ;
                const int ny = y + (ky - HALF) * DIL;
                const int nx = x + (kx - HALF) * DIL;
                if ((unsigned)ny < 64u && (unsigned)nx < 64u)
                    kval = kb[(ny * 64 + nx) * HD + lane];
            }
            v[j] = q * kval;
        }
        #pragma unroll
        for (int m = 16; m >= 1; m >>= 1) {
            const bool up = (lane & m) != 0;
            #pragma unroll
            for (int j = 0; j < m; j++) {
                float send = up ? v[j] : v[j + m];
                float recv = __shfl_xor_sync(0xffffffffu, send, m);
                v[j] = (up ? v[j + m] : v[j]) + recv;
            }
        }
        lgs[batch] = v[0];
    }

    float mx = -1e30f;
    #pragma unroll
    for (int j = 0; j < NL; j++)
        if (j * 32 + lane < L) mx = fmaxf(mx, lgs[j]);
    #pragma unroll
    for (int o = 16; o > 0; o >>= 1)
        mx = fmaxf(mx, __shfl_xor_sync(0xffffffffu, mx, o));

    float e[NL];
    float sum = 0.f;
    #pragma unroll
    for (int j = 0; j < NL; j++) {
        e[j] = (j * 32 + lane < L) ? __expf(lgs[j] - mx) : 0.f;
        sum += e[j];
    }
    #pragma unroll
    for (int o = 16; o > 0; o >>= 1)
        sum += __shfl_xor_sync(0xffffffffu, sum, o);
    const float inv = 1.f / sum;

    float acc = 0.f;
    #pragma unroll
    for (int ky = 0; ky < KSZ; ky++) {
        const int ny = y + (ky - HALF) * DIL;
        #pragma unroll
        for (int kx = 0; kx < KSZ; kx++) {
            const int l = ky * KSZ + kx;
            const int nx = x + (kx - HALF) * DIL;
            if ((unsigned)ny < 64u && (unsigned)nx < 64u) {
                float pl = __shfl_sync(0xffffffffu, e[l >> 5], l & 31) * inv;
                acc += pl * vb[(ny * 64 + nx) * HD + lane];
            }
        }
    }

    g_attn[(b * HW + p) * CDIM + head * HD + lane] = acc;
}

__global__ __launch_bounds__(256) void attn_kernel()
{
    const int lane = threadIdx.x & 31;
    const int wid  = threadIdx.x >> 5;
    const int W    = blockIdx.x * 8 + wid;
    const int p    = W & (HW - 1);
    const int head = (W >> 12) & 7;
    const int b    = W >> 15;

    if (head < 4)      attn_body<5, 1>(lane, b, head, p);
    else if (head < 7) attn_body<7, 2>(lane, b, head, p);
    else               attn_body<9, 3>(lane, b, head, p);
}

// ---------------------------------------------------------------------------
// Kernel 3: output projection, tf32 tensor-core. M=256, K=256, N=4096.
// attn[p][c] is natively col-major ([n][k]) for mma.row.col: no transpose.
// ---------------------------------------------------------------------------
__global__ __launch_bounds__(256) void proj_gemm_kernel(
    const float* __restrict__ pw, const float* __restrict__ pb,
    float* __restrict__ out)
{
    __shared__ unsigned As[64][36];        // [m][k] tf32
    __shared__ unsigned Bs[64][36];        // [n][k] tf32 (col-major B)

    const int tid  = threadIdx.x;
    const int row0 = blockIdx.y * 64;
    const int col0 = blockIdx.x * 64;
    const int b    = blockIdx.z;

    const int wid  = tid >> 5;
    const int lane = tid & 31;
    const int g = lane >> 2, t4 = lane & 3;
    const int m0 = (wid >> 2) * 32;
    const int n0 = (wid & 3) * 16;

    const int am = tid >> 2, ak = (tid & 3) * 8;   // loader mapping (both tiles)

    const float* attb = g_attn + (size_t)b * HW * CDIM;
    float acc[2][2][4] = {};

    for (int k0 = 0; k0 < 256; k0 += 32) {
        {   // A tile: proj_w rows [m][k]
            const float* src = pw + (size_t)(row0 + am) * 256 + k0 + ak;
            float4 v0 = *(const float4*)(src);
            float4 v1 = *(const float4*)(src + 4);
            As[am][ak + 0] = f2tf(v0.x); As[am][ak + 1] = f2tf(v0.y);
            As[am][ak + 2] = f2tf(v0.z); As[am][ak + 3] = f2tf(v0.w);
            As[am][ak + 4] = f2tf(v1.x); As[am][ak + 5] = f2tf(v1.y);
            As[am][ak + 6] = f2tf(v1.z); As[am][ak + 7] = f2tf(v1.w);
        }
        {   // B tile: attn rows [n][k] (k contiguous)
            const float* src = attb + (size_t)(col0 + am) * CDIM + k0 + ak;
            float4 v0 = *(const float4*)(src);
            float4 v1 = *(const float4*)(src + 4);
            Bs[am][ak + 0] = f2tf(v0.x); Bs[am][ak + 1] = f2tf(v0.y);
            Bs[am][ak + 2] = f2tf(v0.z); Bs[am][ak + 3] = f2tf(v0.w);
            Bs[am][ak + 4] = f2tf(v1.x); Bs[am][ak + 5] = f2tf(v1.y);
            Bs[am][ak + 6] = f2tf(v1.z); Bs[am][ak + 7] = f2tf(v1.w);
        }
        __syncthreads();
        #pragma unroll
        for (int ks = 0; ks < 4; ks++) {
            const int kk = ks * 8;
            unsigned a[2][4], bf[2][2];
            #pragma unroll
            for (int mi = 0; mi < 2; mi++) {
                const int mr = m0 + mi * 16;
                a[mi][0] = As[mr + g][kk + t4];
                a[mi][1] = As[mr + g + 8][kk + t4];
                a[mi][2] = As[mr + g][kk + t4 + 4];
                a[mi][3] = As[mr + g + 8][kk + t4 + 4];
            }
            #pragma unroll
            for (int ni = 0; ni < 2; ni++) {
                const int nc = n0 + ni * 8 + g;
                bf[ni][0] = Bs[nc][kk + t4];
                bf[ni][1] = Bs[nc][kk + t4 + 4];
            }
            #pragma unroll
            for (int mi = 0; mi < 2; mi++)
                #pragma unroll
                for (int ni = 0; ni < 2; ni++)
                    mma8(acc[mi][ni], a[mi], bf[ni]);
        }
        __syncthreads();
    }

    // Epilogue: out[b][o][p], float2 stores (d0,d1 / d2,d3 are adjacent p)
    #pragma unroll
    for (int mi = 0; mi < 2; mi++) {
        const int ol = row0 + m0 + mi * 16 + g;
        const int oh = ol + 8;
        const float bl = pb[ol], bh = pb[oh];
        float* basel = out + ((size_t)b * CDIM + ol) * HW;
        float* baseh = out + ((size_t)b * CDIM + oh) * HW;
        #pragma unroll
        for (int ni = 0; ni < 2; ni++) {
            const int p = col0 + n0 + ni * 8 + 2 * t4;
            *(float2*)(basel + p) =
                make_float2(acc[mi][ni][0] + bl, acc[mi][ni][1] + bl);
            *(float2*)(baseh + p) =
                make_float2(acc[mi][ni][2] + bh, acc[mi][ni][3] + bh);
        }
    }
}

// ---------------------------------------------------------------------------
extern "C" void kernel_launch(void* const* d_in, const int* in_sizes, int n_in,
                              void* d_out, int out_size)
{
    const float* x   = (const float*)d_in[0];
    const float* w0  = (const float*)d_in[1];
    const float* bb0 = (const float*)d_in[2];
    const float* w1  = (const float*)d_in[3];
    const float* bb1 = (const float*)d_in[4];
    const float* w2  = (const float*)d_in[5];
    const float* bb2 = (const float*)d_in[6];
    const float* pw  = (const float*)d_in[7];
    const float* pb  = (const float*)d_in[8];
    float* out = (float*)d_out;

    qkv_gemm_kernel<<<dim3(HW / 64, 768 / 64, BATCH), 256>>>(
        x, w0, bb0, w1, bb1, w2, bb2);

    attn_kernel<<<(BATCH * NH * HW) / 8, 256>>>();

    proj_gemm_kernel<<<dim3(HW / 64, CDIM / 64, BATCH), 256>>>(pw, pb, out);
}

// round 6
// speedup vs baseline: 2.6454x; 1.2605x over previous
#include <cuda_runtime.h>

#define HW     4096
#define WIDTH  64
#define CDIM   256
#define NH     8
#define HD     32
#define BATCH  2
#define SCALE  0.17677669529663687f

// Scratch (device globals; no allocation allowed)
__device__ float g_q[BATCH * NH * HW * HD];      // [b, head, p, d]
__device__ float g_k[BATCH * NH * HW * HD];      // [b, head, p, d]
__device__ float g_v[BATCH * NH * HW * HD];      // [b, head, p, d]
__device__ float g_attn[BATCH * HW * CDIM];      // [b, p, c]  c = head*32+d

// ---------------------------------------------------------------------------
// tf32 MMA helpers
// ---------------------------------------------------------------------------
__device__ __forceinline__ unsigned f2tf(float f)
{
    unsigned u;
    asm("cvt.rna.tf32.f32 %0, %1;" : "=r"(u) : "f"(f));
    return u;
}

__device__ __forceinline__ void mma8(float d[4], const unsigned a[4], const unsigned b[2])
{
    asm("mma.sync.aligned.m16n8k8.row.col.f32.tf32.tf32.f32 "
        "{%0,%1,%2,%3}, {%4,%5,%6,%7}, {%8,%9}, {%0,%1,%2,%3};"
        : "+f"(d[0]), "+f"(d[1]), "+f"(d[2]), "+f"(d[3])
        : "r"(a[0]), "r"(a[1]), "r"(a[2]), "r"(a[3]),
          "r"(b[0]), "r"(b[1]));
}

// ---------------------------------------------------------------------------
// Kernel 1: QKV projection, tf32 tensor-core (proven R5 version).
// ---------------------------------------------------------------------------
__global__ __launch_bounds__(256) void qkv_gemm_kernel(
    const float* __restrict__ x,
    const float* __restrict__ w0, const float* __restrict__ bb0,
    const float* __restrict__ w1, const float* __restrict__ bb1,
    const float* __restrict__ w2, const float* __restrict__ bb2)
{
    __shared__ unsigned As[64][36];
    __shared__ unsigned Bs[32][72];
    __shared__ const float* Arow[64];
    __shared__ float* rowDst[64];
    __shared__ float biasS[64];

    const int tid  = threadIdx.x;
    const int row0 = blockIdx.y * 64;
    const int col0 = blockIdx.x * 64;
    const int b    = blockIdx.z;

    if (tid < 64) {
        int M = row0 + tid;
        int t = M >> 8;
        int rem = M & 255;
        int head = rem >> 5, d = rem & 31;
        const float* w; const float* bb;
        if (head < 4)      { w = w0; bb = bb0; }
        else if (head < 7) { w = w1; bb = bb1; }
        else               { w = w2; bb = bb2; }
        Arow[tid]  = w + (size_t)(t * 256 + rem) * 256;
        biasS[tid] = bb[t * 256 + rem];
        float* dst = (t == 0) ? g_q : (t == 1) ? g_k : g_v;
        rowDst[tid] = dst + ((size_t)(b * NH + head) * HW) * HD + d;
    }
    __syncthreads();

    const int wid  = tid >> 5;
    const int lane = tid & 31;
    const int g = lane >> 2, t4 = lane & 3;
    const int m0 = (wid >> 2) * 32;
    const int n0 = (wid & 3) * 16;

    const int am = tid >> 2, ak = (tid & 3) * 8;
    const int bk = tid >> 3, bn = (tid & 7) * 8;

    const float* xb = x + (size_t)b * CDIM * HW;
    float acc[2][2][4] = {};

    for (int k0 = 0; k0 < 256; k0 += 32) {
        {
            const float* src = Arow[am] + k0 + ak;
            float4 v0 = *(const float4*)(src);
            float4 v1 = *(const float4*)(src + 4);
            As[am][ak + 0] = f2tf(v0.x); As[am][ak + 1] = f2tf(v0.y);
            As[am][ak + 2] = f2tf(v0.z); As[am][ak + 3] = f2tf(v0.w);
            As[am][ak + 4] = f2tf(v1.x); As[am][ak + 5] = f2tf(v1.y);
            As[am][ak + 6] = f2tf(v1.z); As[am][ak + 7] = f2tf(v1.w);
        }
        {
            const float* src = xb + (size_t)(k0 + bk) * HW + col0 + bn;
            float4 v0 = *(const float4*)(src);
            float4 v1 = *(const float4*)(src + 4);
            Bs[bk][bn + 0] = f2tf(v0.x); Bs[bk][bn + 1] = f2tf(v0.y);
            Bs[bk][bn + 2] = f2tf(v0.z); Bs[bk][bn + 3] = f2tf(v0.w);
            Bs[bk][bn + 4] = f2tf(v1.x); Bs[bk][bn + 5] = f2tf(v1.y);
            Bs[bk][bn + 6] = f2tf(v1.z); Bs[bk][bn + 7] = f2tf(v1.w);
        }
        __syncthreads();
        #pragma unroll
        for (int ks = 0; ks < 4; ks++) {
            const int kk = ks * 8;
            unsigned a[2][4], bf[2][2];
            #pragma unroll
            for (int mi = 0; mi < 2; mi++) {
                const int mr = m0 + mi * 16;
                a[mi][0] = As[mr + g][kk + t4];
                a[mi][1] = As[mr + g + 8][kk + t4];
                a[mi][2] = As[mr + g][kk + t4 + 4];
                a[mi][3] = As[mr + g + 8][kk + t4 + 4];
            }
            #pragma unroll
            for (int ni = 0; ni < 2; ni++) {
                const int nc = n0 + ni * 8 + g;
                bf[ni][0] = Bs[kk + t4][nc];
                bf[ni][1] = Bs[kk + t4 + 4][nc];
            }
            #pragma unroll
            for (int mi = 0; mi < 2; mi++)
                #pragma unroll
                for (int ni = 0; ni < 2; ni++)
                    mma8(acc[mi][ni], a[mi], bf[ni]);
        }
        __syncthreads();
    }

    #pragma unroll
    for (int mi = 0; mi < 2; mi++) {
        const int rl = m0 + mi * 16 + g;
        const int rh = rl + 8;
        float* dl = rowDst[rl]; const float bl = biasS[rl];
        float* dh = rowDst[rh]; const float bh = biasS[rh];
        #pragma unroll
        for (int ni = 0; ni < 2; ni++) {
            const int p = col0 + n0 + ni * 8 + 2 * t4;
            dl[(size_t)p * HD]       = acc[mi][ni][0] + bl;
            dl[(size_t)(p + 1) * HD] = acc[mi][ni][1] + bl;
            dh[(size_t)p * HD]       = acc[mi][ni][2] + bh;
            dh[(size_t)(p + 1) * HD] = acc[mi][ni][3] + bh;
        }
    }
}

// ---------------------------------------------------------------------------
// Kernel 2: neighborhood attention. One warp per (b, head, pixel); lane = d.
// Interior pixels: all neighbor offsets are compile-time immediates (no ALU,
// no predicates). Border pixels: general path with bounds checks (OOB
// neighbors keep logit = 0 inside the softmax, matching F.unfold zero pad).
// ---------------------------------------------------------------------------
template <int KSZ, int DIL, bool INTERIOR>
__device__ __forceinline__ void attn_body(int lane, int b, int head, int p)
{
    constexpr int L = KSZ * KSZ;
    constexpr int NL = (L + 31) / 32;
    constexpr int HALF = KSZ / 2;

    const int y = p >> 6, x = p & 63;
    const int hb = ((b * NH + head) * HW) * HD;
    const float* __restrict__ kb = g_k + hb;
    const float* __restrict__ vb = g_v + hb;

    const float q = g_q[hb + p * HD + lane] * SCALE;

    float lgs[NL];
    if (INTERIOR) {
        const float* __restrict__ kp = kb + p * HD + lane;
        #pragma unroll
        for (int batch = 0; batch < NL; batch++) {
            float v[32];
            #pragma unroll
            for (int j = 0; j < 32; j++) {
                const int idx = batch * 32 + j;
                if (idx < L) {
                    const int off = ((idx / KSZ - HALF) * DIL * 64
                                   + (idx % KSZ - HALF) * DIL) * HD;
                    v[j] = q * kp[off];
                } else {
                    v[j] = 0.f;
                }
            }
            #pragma unroll
            for (int m = 16; m >= 1; m >>= 1) {
                const bool up = (lane & m) != 0;
                #pragma unroll
                for (int j = 0; j < m; j++) {
                    float send = up ? v[j] : v[j + m];
                    float recv = __shfl_xor_sync(0xffffffffu, send, m);
                    v[j] = (up ? v[j + m] : v[j]) + recv;
                }
            }
            lgs[batch] = v[0];
        }
    } else {
        #pragma unroll
        for (int batch = 0; batch < NL; batch++) {
            float v[32];
            #pragma unroll
            for (int j = 0; j < 32; j++) {
                const int idx = batch * 32 + j;
                float kval = 0.f;
                if (idx < L) {
                    const int ky = idx / KSZ, kx = idx % KSZ;
                    const int ny = y + (ky - HALF) * DIL;
                    const int nx = x + (kx - HALF) * DIL;
                    if ((unsigned)ny < 64u && (unsigned)nx < 64u)
                        kval = kb[(ny * 64 + nx) * HD + lane];
                }
                v[j] = q * kval;
            }
            #pragma unroll
            for (int m = 16; m >= 1; m >>= 1) {
                const bool up = (lane & m) != 0;
                #pragma unroll
                for (int j = 0; j < m; j++) {
                    float send = up ? v[j] : v[j + m];
                    float recv = __shfl_xor_sync(0xffffffffu, send, m);
                    v[j] = (up ? v[j + m] : v[j]) + recv;
                }
            }
            lgs[batch] = v[0];
        }
    }

    float mx = -1e30f;
    #pragma unroll
    for (int j = 0; j < NL; j++)
        if (j * 32 + lane < L) mx = fmaxf(mx, lgs[j]);
    #pragma unroll
    for (int o = 16; o > 0; o >>= 1)
        mx = fmaxf(mx, __shfl_xor_sync(0xffffffffu, mx, o));

    float e[NL];
    float sum = 0.f;
    #pragma unroll
    for (int j = 0; j < NL; j++) {
        e[j] = (j * 32 + lane < L) ? __expf(lgs[j] - mx) : 0.f;
        sum += e[j];
    }
    #pragma unroll
    for (int o = 16; o > 0; o >>= 1)
        sum += __shfl_xor_sync(0xffffffffu, sum, o);
    const float inv = 1.f / sum;

    float acc = 0.f;
    if (INTERIOR) {
        const float* __restrict__ vp = vb + p * HD + lane;
        #pragma unroll
        for (int l = 0; l < L; l++) {
            const int off = ((l / KSZ - HALF) * DIL * 64
                           + (l % KSZ - HALF) * DIL) * HD;
            float pl = __shfl_sync(0xffffffffu, e[l >> 5], l & 31) * inv;
            acc += pl * vp[off];
        }
    } else {
        #pragma unroll
        for (int ky = 0; ky < KSZ; ky++) {
            const int ny = y + (ky - HALF) * DIL;
            #pragma unroll
            for (int kx = 0; kx < KSZ; kx++) {
                const int l = ky * KSZ + kx;
                const int nx = x + (kx - HALF) * DIL;
                if ((unsigned)ny < 64u && (unsigned)nx < 64u) {
                    float pl = __shfl_sync(0xffffffffu, e[l >> 5], l & 31) * inv;
                    acc += pl * vb[(ny * 64 + nx) * HD + lane];
                }
            }
        }
    }

    g_attn[(b * HW + p) * CDIM + head * HD + lane] = acc;
}

template <int KSZ, int DIL>
__device__ __forceinline__ void attn_dispatch(int lane, int b, int head, int p)
{
    constexpr int R = (KSZ / 2) * DIL;
    const int y = p >> 6, x = p & 63;
    if (y >= R && y < 64 - R && x >= R && x < 64 - R)
        attn_body<KSZ, DIL, true>(lane, b, head, p);
    else
        attn_body<KSZ, DIL, false>(lane, b, head, p);
}

__global__ __launch_bounds__(256) void attn_kernel()
{
    const int lane = threadIdx.x & 31;
    const int wid  = threadIdx.x >> 5;
    const int W    = blockIdx.x * 8 + wid;
    const int p    = W & (HW - 1);
    const int head = (W >> 12) & 7;
    const int b    = W >> 15;

    if (head < 4)      attn_dispatch<5, 1>(lane, b, head, p);
    else if (head < 7) attn_dispatch<7, 2>(lane, b, head, p);
    else               attn_dispatch<9, 3>(lane, b, head, p);
}

// ---------------------------------------------------------------------------
// Kernel 3: output projection, tf32 tensor-core (proven R5 version).
// ---------------------------------------------------------------------------
__global__ __launch_bounds__(256) void proj_gemm_kernel(
    const float* __restrict__ pw, const float* __restrict__ pb,
    float* __restrict__ out)
{
    __shared__ unsigned As[64][36];
    __shared__ unsigned Bs[64][36];

    const int tid  = threadIdx.x;
    const int row0 = blockIdx.y * 64;
    const int col0 = blockIdx.x * 64;
    const int b    = blockIdx.z;

    const int wid  = tid >> 5;
    const int lane = tid & 31;
    const int g = lane >> 2, t4 = lane & 3;
    const int m0 = (wid >> 2) * 32;
    const int n0 = (wid & 3) * 16;

    const int am = tid >> 2, ak = (tid & 3) * 8;

    const float* attb = g_attn + (size_t)b * HW * CDIM;
    float acc[2][2][4] = {};

    for (int k0 = 0; k0 < 256; k0 += 32) {
        {
            const float* src = pw + (size_t)(row0 + am) * 256 + k0 + ak;
            float4 v0 = *(const float4*)(src);
            float4 v1 = *(const float4*)(src + 4);
            As[am][ak + 0] = f2tf(v0.x); As[am][ak + 1] = f2tf(v0.y);
            As[am][ak + 2] = f2tf(v0.z); As[am][ak + 3] = f2tf(v0.w);
            As[am][ak + 4] = f2tf(v1.x); As[am][ak + 5] = f2tf(v1.y);
            As[am][ak + 6] = f2tf(v1.z); As[am][ak + 7] = f2tf(v1.w);
        }
        {
            const float* src = attb + (size_t)(col0 + am) * CDIM + k0 + ak;
            float4 v0 = *(const float4*)(src);
            float4 v1 = *(const float4*)(src + 4);
            Bs[am][ak + 0] = f2tf(v0.x); Bs[am][ak + 1] = f2tf(v0.y);
            Bs[am][ak + 2] = f2tf(v0.z); Bs[am][ak + 3] = f2tf(v0.w);
            Bs[am][ak + 4] = f2tf(v1.x); Bs[am][ak + 5] = f2tf(v1.y);
            Bs[am][ak + 6] = f2tf(v1.z); Bs[am][ak + 7] = f2tf(v1.w);
        }
        __syncthreads();
        #pragma unroll
        for (int ks = 0; ks < 4; ks++) {
            const int kk = ks * 8;
            unsigned a[2][4], bf[2][2];
            #pragma unroll
            for (int mi = 0; mi < 2; mi++) {
                const int mr = m0 + mi * 16;
                a[mi][0] = As[mr + g][kk + t4];
                a[mi][1] = As[mr + g + 8][kk + t4];
                a[mi][2] = As[mr + g][kk + t4 + 4];
                a[mi][3] = As[mr + g + 8][kk + t4 + 4];
            }
            #pragma unroll
            for (int ni = 0; ni < 2; ni++) {
                const int nc = n0 + ni * 8 + g;
                bf[ni][0] = Bs[nc][kk + t4];
                bf[ni][1] = Bs[nc][kk + t4 + 4];
            }
            #pragma unroll
            for (int mi = 0; mi < 2; mi++)
                #pragma unroll
                for (int ni = 0; ni < 2; ni++)
                    mma8(acc[mi][ni], a[mi], bf[ni]);
        }
        __syncthreads();
    }

    #pragma unroll
    for (int mi = 0; mi < 2; mi++) {
        const int ol = row0 + m0 + mi * 16 + g;
        const int oh = ol + 8;
        const float bl = pb[ol], bh = pb[oh];
        float* basel = out + ((size_t)b * CDIM + ol) * HW;
        float* baseh = out + ((size_t)b * CDIM + oh) * HW;
        #pragma unroll
        for (int ni = 0; ni < 2; ni++) {
            const int p = col0 + n0 + ni * 8 + 2 * t4;
            *(float2*)(basel + p) =
                make_float2(acc[mi][ni][0] + bl, acc[mi][ni][1] + bl);
            *(float2*)(baseh + p) =
                make_float2(acc[mi][ni][2] + bh, acc[mi][ni][3] + bh);
        }
    }
}

// ---------------------------------------------------------------------------
extern "C" void kernel_launch(void* const* d_in, const int* in_sizes, int n_in,
                              void* d_out, int out_size)
{
    const float* x   = (const float*)d_in[0];
    const float* w0  = (const float*)d_in[1];
    const float* bb0 = (const float*)d_in[2];
    const float* w1  = (const float*)d_in[3];
    const float* bb1 = (const float*)d_in[4];
    const float* w2  = (const float*)d_in[5];
    const float* bb2 = (const float*)d_in[6];
    const float* pw  = (const float*)d_in[7];
    const float* pb  = (const float*)d_in[8];
    float* out = (float*)d_out;

    qkv_gemm_kernel<<<dim3(HW / 64, 768 / 64, BATCH), 256>>>(
        x, w0, bb0, w1, bb1, w2, bb2);

    attn_kernel<<<(BATCH * NH * HW) / 8, 256>>>();

    proj_gemm_kernel<<<dim3(HW / 64, CDIM / 64, BATCH), 256>>>(pw, pb, out);
}